// round 15
// baseline (speedup 1.0000x reference)
#include <cuda_runtime.h>
#include <cuda_bf16.h>
#include <cuda_fp16.h>
#include <math.h>
#include <stdint.h>

// Problem constants
#define BATCH 4
#define SEQ   2048
#define EMBD  1024
#define NHEAD 16
#define HDIM  64
#define MTOT  (BATCH*SEQ)   // 8192
#define QSCALE 0.1803368801111137f   // 0.125 * log2(e)

// ---------------------------------------------------------------------------
// Device scratch
// ---------------------------------------------------------------------------
__device__ __half g_q16[BATCH*NHEAD*SEQ*HDIM];  // [B,H,T,d] (pre-scaled), rounded
__device__ __half g_k16[BATCH*NHEAD*SEQ*HDIM];  // rounded
__device__ __half g_v16[BATCH*NHEAD*SEQ*HDIM];  // rounded

__device__ __half g_x16[MTOT*EMBD];             // x rounded fp16
__device__ __half g_y16[MTOT*EMBD];             // attention out, rounded fp16
__device__ __half g_wt[4*EMBD*EMBD];            // W^T rounded: [z][n][k]

// ---------------------------------------------------------------------------
// PTX helpers (arch-generic only — harness compiles compute_103)
// ---------------------------------------------------------------------------
__device__ __forceinline__ uint32_t smem_u32(const void* p) {
    uint32_t a;
    asm("{ .reg .u64 t; cvta.to.shared.u64 t, %1; cvt.u32.u64 %0, t; }"
        : "=r"(a) : "l"(p));
    return a;
}
__device__ __forceinline__ void cp16(uint32_t dst, const void* src) {
    asm volatile("cp.async.cg.shared.global [%0], [%1], 16;"
                 :: "r"(dst), "l"(src) : "memory");
}
#define CP_COMMIT() asm volatile("cp.async.commit_group;" ::: "memory")
#define CP_WAIT(n)  asm volatile("cp.async.wait_group %0;" :: "n"(n) : "memory")

#define LDSM_X4(r0, r1, r2, r3, addr) \
    asm volatile("ldmatrix.sync.aligned.m8n8.x4.shared.b16 {%0,%1,%2,%3}, [%4];" \
        : "=r"(r0), "=r"(r1), "=r"(r2), "=r"(r3) : "r"(addr))
#define LDSM_X4_T(r0, r1, r2, r3, addr) \
    asm volatile("ldmatrix.sync.aligned.m8n8.x4.trans.shared.b16 {%0,%1,%2,%3}, [%4];" \
        : "=r"(r0), "=r"(r1), "=r"(r2), "=r"(r3) : "r"(addr))

#define MMA_FP16(d, a0, a1, a2, a3, b0, b1) \
    asm volatile("mma.sync.aligned.m16n8k16.row.col.f32.f16.f16.f32 " \
        "{%0,%1,%2,%3}, {%4,%5,%6,%7}, {%8,%9}, {%0,%1,%2,%3};" \
        : "+f"((d)[0]), "+f"((d)[1]), "+f"((d)[2]), "+f"((d)[3]) \
        : "r"(a0), "r"(a1), "r"(a2), "r"(a3), "r"(b0), "r"(b1))

__device__ __forceinline__ uint32_t pack_h2(float a, float b) {
    uint32_t r;
    asm("cvt.rn.f16x2.f32 %0, %1, %2;" : "=r"(r) : "f"(b), "f"(a));
    return r;
}
// 2^x on both fp16 halves
__device__ __forceinline__ uint32_t ex2h2(uint32_t x) {
    uint32_t y;
    asm("ex2.approx.f16x2 %0, %1;" : "=r"(y) : "r"(x));
    return y;
}
// sum both fp16 halves into fp32
__device__ __forceinline__ float h2sumf(uint32_t r) {
    __half2 h = *(__half2*)&r;
    float2 f = __half22float2(h);
    return f.x + f.y;
}

// ---------------------------------------------------------------------------
// Fused prep: z=0..3 -> Wt[z][n][k] = fp16(W[k][n]);  z=4 -> x round fp16
// ---------------------------------------------------------------------------
__global__ __launch_bounds__(256) void prep_kernel(
    const float* __restrict__ x,
    const float* __restrict__ Wq, const float* __restrict__ Wk,
    const float* __restrict__ Wv, const float* __restrict__ Wp)
{
    const int z = blockIdx.z;
    if (z < 4) {
        __shared__ float ts[32][33];
        const float* W = (z == 0) ? Wq : (z == 1) ? Wk : (z == 2) ? Wv : Wp;
        __half* ot = g_wt + (size_t)z * EMBD * EMBD;
        const int k0 = blockIdx.x * 32;
        const int n0 = blockIdx.y * 32;
        const int tx = threadIdx.x & 31;
        const int ty = threadIdx.x >> 5;
#pragma unroll
        for (int i = 0; i < 4; i++) {
            int r = ty + i * 8;
            ts[r][tx] = W[(size_t)(k0 + r) * EMBD + n0 + tx];
        }
        __syncthreads();
#pragma unroll
        for (int i = 0; i < 4; i++) {
            int r = ty + i * 8;
            ot[(size_t)(n0 + r) * EMBD + k0 + tx] = __float2half_rn(ts[tx][r]);
        }
    } else {
        // round x: 1024 blocks x 2048 float4 = 8M elements
        const int bid = blockIdx.y * 32 + blockIdx.x;
        const int base = bid * 2048;
#pragma unroll
        for (int it = 0; it < 8; it++) {
            int i = base + it * 256 + threadIdx.x;
            float4 v = ((const float4*)x)[i];
            __half2* op = (__half2*)(g_x16 + (size_t)i * 4);
            op[0] = __half2{__float2half_rn(v.x), __float2half_rn(v.y)};
            op[1] = __half2{__float2half_rn(v.z), __float2half_rn(v.w)};
        }
    }
}

// ---------------------------------------------------------------------------
// Single-product fp16 GEMM core: C = A @ B^T, 128x128x32 tiles,
// 4-stage cp.async ring, ONE __syncthreads per iteration, loads AFTER compute.
// ---------------------------------------------------------------------------
#define BM 128
#define BN 128
#define BK 32
#define NCHUNK (EMBD / BK)
#define ROWB  80

#define Q_SA   0
#define Q_SB   10240
#define Q_STG  20480
#define GEMM_SMEM (4 * Q_STG)   // 81920

__device__ __forceinline__ void load_stage_1p(
    uint32_t stage_base,
    const __half* __restrict__ A, const __half* __restrict__ B,
    int m0, int n0, int kc, int tid)
{
#pragma unroll
    for (int i = 0; i < 2; i++) {
        int idx = tid + i * 256;
        int r  = idx >> 2;
        int ch = idx & 3;
        uint32_t d = stage_base + (uint32_t)(r * ROWB + ch * 16);
        cp16(d + Q_SA, A + (size_t)(m0 + r) * EMBD + kc + ch * 8);
        cp16(d + Q_SB, B + (size_t)(n0 + r) * EMBD + kc + ch * 8);
    }
    CP_COMMIT();
}

struct GemmAcc { float a[4][4][4]; };

__device__ __forceinline__ void gemm_1p_mainloop(
    GemmAcc& ac, uint32_t sb,
    const __half* __restrict__ A, const __half* __restrict__ B,
    int m0, int n0, int m_w, int n_w, int lane, int tid)
{
#pragma unroll
    for (int i = 0; i < 4; i++)
#pragma unroll
        for (int j = 0; j < 4; j++)
#pragma unroll
            for (int e = 0; e < 4; e++) ac.a[i][j][e] = 0.f;

    load_stage_1p(sb + 0 * Q_STG, A, B, m0, n0, 0 * BK, tid);
    load_stage_1p(sb + 1 * Q_STG, A, B, m0, n0, 1 * BK, tid);
    load_stage_1p(sb + 2 * Q_STG, A, B, m0, n0, 2 * BK, tid);

    const uint32_t a_row_off = (uint32_t)((m_w + (lane & 15)) * ROWB) + ((lane >> 4) * 16);
    const uint32_t b_row_off = (uint32_t)((n_w + (lane & 7) + ((lane >> 4) << 3)) * ROWB)
                             + (((lane >> 3) & 1) * 16);

    for (int c = 0; c < NCHUNK; c++) {
        if (c >= NCHUNK - 3) CP_WAIT(0); else CP_WAIT(2);
        __syncthreads();    // single barrier: 4-stage ring makes write-target safe

        const uint32_t stb = sb + (uint32_t)(c & 3) * Q_STG;
#pragma unroll
        for (int ks = 0; ks < 2; ks++) {
            uint32_t aa[4][4], bb[4][2];
            const uint32_t kso = (uint32_t)(ks * 32);
#pragma unroll
            for (int i = 0; i < 4; i++) {
                uint32_t aaddr = stb + Q_SA + a_row_off + (uint32_t)(i * 16 * ROWB) + kso;
                LDSM_X4(aa[i][0], aa[i][1], aa[i][2], aa[i][3], aaddr);
            }
#pragma unroll
            for (int jp = 0; jp < 2; jp++) {
                uint32_t baddr = stb + Q_SB + b_row_off + (uint32_t)(jp * 16 * ROWB) + kso;
                LDSM_X4(bb[2*jp][0], bb[2*jp][1], bb[2*jp+1][0], bb[2*jp+1][1], baddr);
            }
#pragma unroll
            for (int i = 0; i < 4; i++)
#pragma unroll
                for (int j = 0; j < 4; j++)
                    MMA_FP16(ac.a[i][j], aa[i][0], aa[i][1], aa[i][2], aa[i][3],
                             bb[j][0], bb[j][1]);
        }
        if (c + 3 < NCHUNK)
            load_stage_1p(sb + (uint32_t)((c + 3) & 3) * Q_STG, A, B, m0, n0,
                          (c + 3) * BK, tid);
    }
}

__global__ __launch_bounds__(256, 2) void gemm_qkv(
    const __half* __restrict__ A, const __half* __restrict__ B_all)
{
    extern __shared__ char smch[];
    const uint32_t sb = smem_u32(smch);

    const int tid  = threadIdx.x;
    const int lane = tid & 31;
    const int wid  = tid >> 5;
    const int m_w  = (wid & 1) * 64;
    const int n_w  = (wid >> 1) * 32;
    const int n0 = blockIdx.x * BN;
    const int m0 = blockIdx.y * BM;
    const int z  = blockIdx.z;
    const __half* B = B_all + (size_t)z * EMBD * EMBD;

    GemmAcc ac;
    gemm_1p_mainloop(ac, sb, A, B, m0, n0, m_w, n_w, lane, tid);

    const float scale = (z == 0) ? QSCALE : 1.0f;
    __half* dst = (z == 0) ? g_q16 : (z == 1) ? g_k16 : g_v16;

    const int b  = m0 >> 11;
    const int rr = m0 + m_w + (lane >> 2);
#pragma unroll
    for (int i = 0; i < 4; i++) {
        const int r0 = rr + i * 16;
        const int t0 = r0 & 2047;
#pragma unroll
        for (int j = 0; j < 4; j++) {
            const int cc = n0 + n_w + j * 8 + 2 * (lane & 3);
            const int h  = cc >> 6;
            const int dd = cc & 63;
            size_t i0 = (((size_t)(b * NHEAD + h) * SEQ + t0) << 6) + dd;
            size_t i1 = i0 + (8 << 6);
            *(__half2*)&dst[i0] =
                __half2{__float2half_rn(ac.a[i][j][0] * scale),
                        __float2half_rn(ac.a[i][j][1] * scale)};
            *(__half2*)&dst[i1] =
                __half2{__float2half_rn(ac.a[i][j][2] * scale),
                        __float2half_rn(ac.a[i][j][3] * scale)};
        }
    }
}

__global__ __launch_bounds__(256, 2) void gemm_proj(
    const __half* __restrict__ A, const __half* __restrict__ B,
    const float* __restrict__ bias, float* __restrict__ outp)
{
    extern __shared__ char smch[];
    const uint32_t sb = smem_u32(smch);

    const int tid  = threadIdx.x;
    const int lane = tid & 31;
    const int wid  = tid >> 5;
    const int m_w  = (wid & 1) * 64;
    const int n_w  = (wid >> 1) * 32;
    const int n0 = blockIdx.x * BN;
    const int m0 = blockIdx.y * BM;

    GemmAcc ac;
    gemm_1p_mainloop(ac, sb, A, B, m0, n0, m_w, n_w, lane, tid);

    const int rr = m0 + m_w + (lane >> 2);
#pragma unroll
    for (int i = 0; i < 4; i++) {
        const int r0 = rr + i * 16;
#pragma unroll
        for (int j = 0; j < 4; j++) {
            const int cc = n0 + n_w + j * 8 + 2 * (lane & 3);
            float2 bv = *(const float2*)&bias[cc];
            float* p = outp + (size_t)r0 * EMBD + cc;
            *(float2*)p = make_float2(ac.a[i][j][0] + bv.x, ac.a[i][j][1] + bv.y);
            *(float2*)(p + 8 * EMBD) =
                make_float2(ac.a[i][j][2] + bv.x, ac.a[i][j][3] + bv.y);
        }
    }
}

// ---------------------------------------------------------------------------
// Tensor-core causal flash attention — MAX-FREE softmax, single-rounded Q.
// S = Q16 K16 (1 fp16 product). P = 2^s via ex2.f16x2.
// l accumulated on the FMA pipe (cvt+add from packed P, exact fp16->fp32),
// with the 4-thread shuffle reduction deferred to the epilogue.
// O += P V (1 product). Br=64 (4 warps), Bc=64, 3 CTAs/SM, Q frags in regs.
// ---------------------------------------------------------------------------
#define ROWP 144      // 64 elems * 2B = 128B, +16B pad
#define SQ    0
#define STAGE0 9216
#define ASTG  18432   // per stage: K, V each 64*144=9216
#define OFF_K 0
#define OFF_V 9216
#define ATTN_SMEM (STAGE0 + 2 * ASTG)   // 46080

__global__ __launch_bounds__(128, 3) void attn_tc()
{
    extern __shared__ char smch[];
    const uint32_t sb = smem_u32(smch);

    const int tid  = threadIdx.x;
    const int lane = tid & 31;
    const int w    = tid >> 5;          // 0..3

    const int qt = gridDim.x - 1 - blockIdx.x;  // heavy tiles first
    const int h  = blockIdx.y;
    const int b  = blockIdx.z;
    const int q0 = qt * 64;
    const int kt_end = qt + 1;

    const size_t hb = ((size_t)(b * NHEAD + h)) * SEQ * HDIM;
    const __half* qg = g_q16 + hb + (size_t)q0 * HDIM;
    const __half* kg = g_k16 + hb;
    const __half* vg = g_v16 + hb;

    // --- issue Q loads (group 0): 64 rows x 8 chunks ---
#pragma unroll
    for (int i = 0; i < 4; i++) {
        int idx = tid + i * 128;       // 512
        int r = idx >> 3, ch = idx & 7;
        uint32_t d = sb + SQ + (uint32_t)(r * ROWP + ch * 16);
        cp16(d, qg + (size_t)r * HDIM + ch * 8);
    }
    CP_COMMIT();

    // --- prologue K/V stages for kt=0,1 (stage 1 may be empty group) ---
#pragma unroll
    for (int st = 0; st < 2; st++) {
        if (st < kt_end) {
            uint32_t base = sb + STAGE0 + st * ASTG;
            int k0 = st * 64;
#pragma unroll
            for (int i = 0; i < 4; i++) {
                int idx = tid + i * 128;   // 512: 64 rows x 8 chunks
                int r = idx >> 3, ch = idx & 7;
                uint32_t d = base + (uint32_t)(r * ROWP + ch * 16);
                size_t g = (size_t)(k0 + r) * HDIM + ch * 8;
                cp16(d + OFF_K, kg + g);
                cp16(d + OFF_V, vg + g);
            }
        }
        CP_COMMIT();
    }

    // --- Q A-frags into registers (cached across kt loop) ---
    CP_WAIT(2);
    __syncthreads();
    uint32_t qh[4][4];
    {
        uint32_t arow = sb + SQ + (uint32_t)((w * 16 + (lane & 15)) * ROWP) + ((lane >> 4) * 16);
#pragma unroll
        for (int t = 0; t < 4; t++)
            LDSM_X4(qh[t][0], qh[t][1], qh[t][2], qh[t][3], arow + t * 32);
    }

    float o[8][4];
#pragma unroll
    for (int j = 0; j < 8; j++)
#pragma unroll
        for (int e = 0; e < 4; e++) o[j][e] = 0.f;
    float l0s = 0.f, l1s = 0.f;   // per-thread partials (16 cols each row)

    const int warp_rmin = q0 + w * 16;
    const int row0 = warp_rmin + (lane >> 2);    // rows for c0/c1
    const int row1 = row0 + 8;                   // rows for c2/c3
    const int kcol = 2 * (lane & 3);

    for (int kt = 0; kt < kt_end; kt++) {
        if (kt + 1 < kt_end) CP_WAIT(1); else CP_WAIT(0);
        __syncthreads();

        const int k0 = kt * 64;
        const uint32_t stg = sb + STAGE0 + (kt & 1) * ASTG;

        // ---- S = Q K^T (single fp16 product; X4 K loads feed 2 k-slices) ----
        float s[8][4];
#pragma unroll
        for (int j = 0; j < 8; j++)
#pragma unroll
            for (int e = 0; e < 4; e++) s[j][e] = 0.f;

        const uint32_t kbase = stg + OFF_K + (uint32_t)((lane & 7) * ROWP) + ((lane >> 3) * 16);
#pragma unroll
        for (int tt = 0; tt < 2; tt++) {
#pragma unroll
            for (int j = 0; j < 8; j++) {
                uint32_t kb[4];
                uint32_t ba = kbase + (uint32_t)(j * 8 * ROWP) + tt * 64;
                LDSM_X4(kb[0], kb[1], kb[2], kb[3], ba);
                MMA_FP16(s[j], qh[2*tt][0],   qh[2*tt][1],   qh[2*tt][2],   qh[2*tt][3],   kb[0], kb[1]);
                MMA_FP16(s[j], qh[2*tt+1][0], qh[2*tt+1][1], qh[2*tt+1][2], qh[2*tt+1][3], kb[2], kb[3]);
            }
        }

        // ---- causal mask (diagonal tile only) ----
        if (kt == kt_end - 1) {
#pragma unroll
            for (int j = 0; j < 8; j++) {
                int kg2 = k0 + j * 8 + kcol;
                if (kg2     > row0) s[j][0] = -1e30f;
                if (kg2 + 1 > row0) s[j][1] = -1e30f;
                if (kg2     > row1) s[j][2] = -1e30f;
                if (kg2 + 1 > row1) s[j][3] = -1e30f;
            }
        }

        // ---- P = 2^s directly (max-free: logits bounded, fp16 holds it) ----
        uint32_t pa[4][4];
#pragma unroll
        for (int t = 0; t < 4; t++) {
            pa[t][0] = ex2h2(pack_h2(s[2*t][0],   s[2*t][1]));
            pa[t][1] = ex2h2(pack_h2(s[2*t][2],   s[2*t][3]));
            pa[t][2] = ex2h2(pack_h2(s[2*t+1][0], s[2*t+1][1]));
            pa[t][3] = ex2h2(pack_h2(s[2*t+1][2], s[2*t+1][3]));
        }

        // ---- l partials on FMA pipe (exact fp16->fp32 cvt, fp32 adds) ----
#pragma unroll
        for (int t = 0; t < 4; t++) {
            l0s += h2sumf(pa[t][0]) + h2sumf(pa[t][2]);
            l1s += h2sumf(pa[t][1]) + h2sumf(pa[t][3]);
        }

        // ---- O += P @ V (single fp16 product, x4.trans) ----
        const uint32_t vbase = stg + OFF_V + (uint32_t)((lane & 15) * ROWP) + ((lane >> 4) * 16);
#pragma unroll
        for (int t = 0; t < 4; t++) {
            const uint32_t vt = vbase + (uint32_t)(t * 16 * ROWP);
#pragma unroll
            for (int jp = 0; jp < 4; jp++) {
                uint32_t v0, v1, v2, v3;
                LDSM_X4_T(v0, v1, v2, v3, vt + jp * 32);
                MMA_FP16(o[2*jp],   pa[t][0], pa[t][1], pa[t][2], pa[t][3], v0, v1);
                MMA_FP16(o[2*jp+1], pa[t][0], pa[t][1], pa[t][2], pa[t][3], v2, v3);
            }
        }

        __syncthreads();
        if (kt + 2 < kt_end) {
            uint32_t base = sb + STAGE0 + (kt & 1) * ASTG;
            int kn = (kt + 2) * 64;
#pragma unroll
            for (int i = 0; i < 4; i++) {
                int idx = tid + i * 128;
                int r = idx >> 3, ch = idx & 7;
                uint32_t d = base + (uint32_t)(r * ROWP + ch * 16);
                size_t g = (size_t)(kn + r) * HDIM + ch * 8;
                cp16(d + OFF_K, kg + g);
                cp16(d + OFF_V, vg + g);
            }
            CP_COMMIT();
        } else {
            CP_COMMIT();   // keep group count consistent with wait logic
        }
    }

    // ---- deferred l reduction (4 threads per row: lane^1, lane^2) ----
    l0s += __shfl_xor_sync(0xffffffffu, l0s, 1);
    l0s += __shfl_xor_sync(0xffffffffu, l0s, 2);
    l1s += __shfl_xor_sync(0xffffffffu, l1s, 1);
    l1s += __shfl_xor_sync(0xffffffffu, l1s, 2);

    // ---- epilogue: O / l -> rounded fp16 y [B,T,C] ----
    const float rn0 = 1.0f / l0s;
    const float rn1 = 1.0f / l1s;
    const int cbase = h * HDIM + kcol;
#pragma unroll
    for (int j = 0; j < 8; j++) {
        int cc = cbase + j * 8;
        size_t i0 = ((size_t)b * SEQ + row0) * EMBD + cc;
        size_t i1 = ((size_t)b * SEQ + row1) * EMBD + cc;
        *(__half2*)&g_y16[i0] = __half2{__float2half_rn(o[j][0] * rn0),
                                        __float2half_rn(o[j][1] * rn0)};
        *(__half2*)&g_y16[i1] = __half2{__float2half_rn(o[j][2] * rn1),
                                        __float2half_rn(o[j][3] * rn1)};
    }
}

// ---------------------------------------------------------------------------
extern "C" void kernel_launch(void* const* d_in, const int* in_sizes, int n_in,
                              void* d_out, int out_size)
{
    const float* x  = (const float*)d_in[0];
    const float* Wq = (const float*)d_in[1];
    const float* Wk = (const float*)d_in[2];
    const float* Wv = (const float*)d_in[3];
    const float* Wp = (const float*)d_in[4];
    const float* bp = (const float*)d_in[5];
    float* out = (float*)d_out;

    cudaFuncSetAttribute(gemm_qkv,  cudaFuncAttributeMaxDynamicSharedMemorySize, GEMM_SMEM);
    cudaFuncSetAttribute(gemm_proj, cudaFuncAttributeMaxDynamicSharedMemorySize, GEMM_SMEM);
    cudaFuncSetAttribute(attn_tc,   cudaFuncAttributeMaxDynamicSharedMemorySize, ATTN_SMEM);

    __half *x16, *y16, *wt;
    cudaGetSymbolAddress((void**)&x16, g_x16);
    cudaGetSymbolAddress((void**)&y16, g_y16);
    cudaGetSymbolAddress((void**)&wt,  g_wt);

    // 1) fused prep: round x + transpose/round all 4 weight matrices
    prep_kernel<<<dim3(32, 32, 5), 256>>>(x, Wq, Wk, Wv, Wp);
    // 2) QKV projections (single product) -> Q (pre-scaled) / K / V fp16
    gemm_qkv<<<dim3(EMBD / BN, MTOT / BM, 3), 256, GEMM_SMEM>>>(x16, wt);
    // 3) tensor-core flash attention (max-free softmax, FMA-pipe l)
    attn_tc<<<dim3(SEQ / 64, NHEAD, BATCH), 128, ATTN_SMEM>>>();
    // 4) output projection + bias (single product)
    gemm_proj<<<dim3(EMBD / BN, MTOT / BM), 256, GEMM_SMEM>>>(
        y16, wt + 3 * (size_t)EMBD * EMBD, bp, out);
}

// round 16
// speedup vs baseline: 1.0183x; 1.0183x over previous
#include <cuda_runtime.h>
#include <cuda_bf16.h>
#include <cuda_fp16.h>
#include <math.h>
#include <stdint.h>

// Problem constants
#define BATCH 4
#define SEQ   2048
#define EMBD  1024
#define NHEAD 16
#define HDIM  64
#define MTOT  (BATCH*SEQ)   // 8192
#define QSCALE 0.1803368801111137f   // 0.125 * log2(e)

// ---------------------------------------------------------------------------
// Device scratch
// ---------------------------------------------------------------------------
__device__ __half g_q16[BATCH*NHEAD*SEQ*HDIM];  // [B,H,T,d] (pre-scaled), rounded
__device__ __half g_k16[BATCH*NHEAD*SEQ*HDIM];  // rounded
__device__ __half g_v16[BATCH*NHEAD*SEQ*HDIM];  // rounded

__device__ __half g_x16[MTOT*EMBD];             // x rounded fp16
__device__ __half g_y16[MTOT*EMBD];             // attention out, rounded fp16
__device__ __half g_wt[4*EMBD*EMBD];            // W^T rounded: [z][n][k]

// ---------------------------------------------------------------------------
// PTX helpers (arch-generic only — harness compiles compute_103)
// ---------------------------------------------------------------------------
__device__ __forceinline__ uint32_t smem_u32(const void* p) {
    uint32_t a;
    asm("{ .reg .u64 t; cvta.to.shared.u64 t, %1; cvt.u32.u64 %0, t; }"
        : "=r"(a) : "l"(p));
    return a;
}
__device__ __forceinline__ void cp16(uint32_t dst, const void* src) {
    asm volatile("cp.async.cg.shared.global [%0], [%1], 16;"
                 :: "r"(dst), "l"(src) : "memory");
}
#define CP_COMMIT() asm volatile("cp.async.commit_group;" ::: "memory")
#define CP_WAIT(n)  asm volatile("cp.async.wait_group %0;" :: "n"(n) : "memory")

#define LDSM_X4(r0, r1, r2, r3, addr) \
    asm volatile("ldmatrix.sync.aligned.m8n8.x4.shared.b16 {%0,%1,%2,%3}, [%4];" \
        : "=r"(r0), "=r"(r1), "=r"(r2), "=r"(r3) : "r"(addr))
#define LDSM_X4_T(r0, r1, r2, r3, addr) \
    asm volatile("ldmatrix.sync.aligned.m8n8.x4.trans.shared.b16 {%0,%1,%2,%3}, [%4];" \
        : "=r"(r0), "=r"(r1), "=r"(r2), "=r"(r3) : "r"(addr))

#define MMA_FP16(d, a0, a1, a2, a3, b0, b1) \
    asm volatile("mma.sync.aligned.m16n8k16.row.col.f32.f16.f16.f32 " \
        "{%0,%1,%2,%3}, {%4,%5,%6,%7}, {%8,%9}, {%0,%1,%2,%3};" \
        : "+f"((d)[0]), "+f"((d)[1]), "+f"((d)[2]), "+f"((d)[3]) \
        : "r"(a0), "r"(a1), "r"(a2), "r"(a3), "r"(b0), "r"(b1))

__device__ __forceinline__ uint32_t pack_h2(float a, float b) {
    uint32_t r;
    asm("cvt.rn.f16x2.f32 %0, %1, %2;" : "=r"(r) : "f"(b), "f"(a));
    return r;
}
// 2^x on both fp16 halves
__device__ __forceinline__ uint32_t ex2h2(uint32_t x) {
    uint32_t y;
    asm("ex2.approx.f16x2 %0, %1;" : "=r"(y) : "r"(x));
    return y;
}

// ---------------------------------------------------------------------------
// Fused prep: z=0..3 -> Wt[z][n][k] = fp16(W[k][n]);  z=4 -> x round fp16
// ---------------------------------------------------------------------------
__global__ __launch_bounds__(256) void prep_kernel(
    const float* __restrict__ x,
    const float* __restrict__ Wq, const float* __restrict__ Wk,
    const float* __restrict__ Wv, const float* __restrict__ Wp)
{
    const int z = blockIdx.z;
    if (z < 4) {
        __shared__ float ts[32][33];
        const float* W = (z == 0) ? Wq : (z == 1) ? Wk : (z == 2) ? Wv : Wp;
        __half* ot = g_wt + (size_t)z * EMBD * EMBD;
        const int k0 = blockIdx.x * 32;
        const int n0 = blockIdx.y * 32;
        const int tx = threadIdx.x & 31;
        const int ty = threadIdx.x >> 5;
#pragma unroll
        for (int i = 0; i < 4; i++) {
            int r = ty + i * 8;
            ts[r][tx] = W[(size_t)(k0 + r) * EMBD + n0 + tx];
        }
        __syncthreads();
#pragma unroll
        for (int i = 0; i < 4; i++) {
            int r = ty + i * 8;
            ot[(size_t)(n0 + r) * EMBD + k0 + tx] = __float2half_rn(ts[tx][r]);
        }
    } else {
        // round x: 1024 blocks x 2048 float4 = 8M elements
        const int bid = blockIdx.y * 32 + blockIdx.x;
        const int base = bid * 2048;
#pragma unroll
        for (int it = 0; it < 8; it++) {
            int i = base + it * 256 + threadIdx.x;
            float4 v = ((const float4*)x)[i];
            __half2* op = (__half2*)(g_x16 + (size_t)i * 4);
            op[0] = __half2{__float2half_rn(v.x), __float2half_rn(v.y)};
            op[1] = __half2{__float2half_rn(v.z), __float2half_rn(v.w)};
        }
    }
}

// ---------------------------------------------------------------------------
// Single-product fp16 GEMM: C = A @ B^T, 128x128x32 tiles.
// ---------------------------------------------------------------------------
#define BM 128
#define BN 128
#define BK 32
#define NCHUNK (EMBD / BK)
#define ROWB  80

#define Q_SA   0
#define Q_SB   10240
#define Q_STG  20480
#define GEMM1_SMEM (4 * Q_STG)   // 81920 (qkv: 4-stage)
#define GEMM2_SMEM (5 * Q_STG)   // 102400 (proj: 5-stage, deeper prefetch)

__device__ __forceinline__ void load_stage_1p(
    uint32_t stage_base,
    const __half* __restrict__ A, const __half* __restrict__ B,
    int m0, int n0, int kc, int tid)
{
#pragma unroll
    for (int i = 0; i < 2; i++) {
        int idx = tid + i * 256;
        int r  = idx >> 2;
        int ch = idx & 3;
        uint32_t d = stage_base + (uint32_t)(r * ROWB + ch * 16);
        cp16(d + Q_SA, A + (size_t)(m0 + r) * EMBD + kc + ch * 8);
        cp16(d + Q_SB, B + (size_t)(n0 + r) * EMBD + kc + ch * 8);
    }
    CP_COMMIT();
}

struct GemmAcc { float a[4][4][4]; };

// compute one BK chunk from resident stage
__device__ __forceinline__ void gemm_chunk(
    GemmAcc& ac, uint32_t stb, uint32_t a_row_off, uint32_t b_row_off)
{
#pragma unroll
    for (int ks = 0; ks < 2; ks++) {
        uint32_t aa[4][4], bb[4][2];
        const uint32_t kso = (uint32_t)(ks * 32);
#pragma unroll
        for (int i = 0; i < 4; i++) {
            uint32_t aaddr = stb + Q_SA + a_row_off + (uint32_t)(i * 16 * ROWB) + kso;
            LDSM_X4(aa[i][0], aa[i][1], aa[i][2], aa[i][3], aaddr);
        }
#pragma unroll
        for (int jp = 0; jp < 2; jp++) {
            uint32_t baddr = stb + Q_SB + b_row_off + (uint32_t)(jp * 16 * ROWB) + kso;
            LDSM_X4(bb[2*jp][0], bb[2*jp][1], bb[2*jp+1][0], bb[2*jp+1][1], baddr);
        }
#pragma unroll
        for (int i = 0; i < 4; i++)
#pragma unroll
            for (int j = 0; j < 4; j++)
                MMA_FP16(ac.a[i][j], aa[i][0], aa[i][1], aa[i][2], aa[i][3],
                         bb[j][0], bb[j][1]);
    }
}

__global__ __launch_bounds__(256, 2) void gemm_qkv(
    const __half* __restrict__ A, const __half* __restrict__ B_all)
{
    extern __shared__ char smch[];
    const uint32_t sb = smem_u32(smch);

    const int tid  = threadIdx.x;
    const int lane = tid & 31;
    const int wid  = tid >> 5;
    const int m_w  = (wid & 1) * 64;
    const int n_w  = (wid >> 1) * 32;
    const int n0 = blockIdx.x * BN;
    const int m0 = blockIdx.y * BM;
    const int z  = blockIdx.z;
    const __half* B = B_all + (size_t)z * EMBD * EMBD;

    GemmAcc ac;
#pragma unroll
    for (int i = 0; i < 4; i++)
#pragma unroll
        for (int j = 0; j < 4; j++)
#pragma unroll
            for (int e = 0; e < 4; e++) ac.a[i][j][e] = 0.f;

    load_stage_1p(sb + 0 * Q_STG, A, B, m0, n0, 0 * BK, tid);
    load_stage_1p(sb + 1 * Q_STG, A, B, m0, n0, 1 * BK, tid);
    load_stage_1p(sb + 2 * Q_STG, A, B, m0, n0, 2 * BK, tid);

    const uint32_t a_row_off = (uint32_t)((m_w + (lane & 15)) * ROWB) + ((lane >> 4) * 16);
    const uint32_t b_row_off = (uint32_t)((n_w + (lane & 7) + ((lane >> 4) << 3)) * ROWB)
                             + (((lane >> 3) & 1) * 16);

    for (int c = 0; c < NCHUNK; c++) {
        if (c >= NCHUNK - 3) CP_WAIT(0); else CP_WAIT(2);
        __syncthreads();    // single barrier: 4-stage ring makes write-target safe

        gemm_chunk(ac, sb + (uint32_t)(c & 3) * Q_STG, a_row_off, b_row_off);

        if (c + 3 < NCHUNK)
            load_stage_1p(sb + (uint32_t)((c + 3) & 3) * Q_STG, A, B, m0, n0,
                          (c + 3) * BK, tid);
    }

    const float scale = (z == 0) ? QSCALE : 1.0f;
    __half* dst = (z == 0) ? g_q16 : (z == 1) ? g_k16 : g_v16;

    const int b  = m0 >> 11;
    const int rr = m0 + m_w + (lane >> 2);
#pragma unroll
    for (int i = 0; i < 4; i++) {
        const int r0 = rr + i * 16;
        const int t0 = r0 & 2047;
#pragma unroll
        for (int j = 0; j < 4; j++) {
            const int cc = n0 + n_w + j * 8 + 2 * (lane & 3);
            const int h  = cc >> 6;
            const int dd = cc & 63;
            size_t i0 = (((size_t)(b * NHEAD + h) * SEQ + t0) << 6) + dd;
            size_t i1 = i0 + (8 << 6);
            *(__half2*)&dst[i0] =
                __half2{__float2half_rn(ac.a[i][j][0] * scale),
                        __float2half_rn(ac.a[i][j][1] * scale)};
            *(__half2*)&dst[i1] =
                __half2{__float2half_rn(ac.a[i][j][2] * scale),
                        __float2half_rn(ac.a[i][j][3] * scale)};
        }
    }
}

__global__ __launch_bounds__(256, 2) void gemm_proj(
    const __half* __restrict__ A, const __half* __restrict__ B,
    const float* __restrict__ bias, float* __restrict__ outp)
{
    extern __shared__ char smch[];
    const uint32_t sb = smem_u32(smch);

    const int tid  = threadIdx.x;
    const int lane = tid & 31;
    const int wid  = tid >> 5;
    const int m_w  = (wid & 1) * 64;
    const int n_w  = (wid >> 1) * 32;
    const int n0 = blockIdx.x * BN;
    const int m0 = blockIdx.y * BM;

    GemmAcc ac;
#pragma unroll
    for (int i = 0; i < 4; i++)
#pragma unroll
        for (int j = 0; j < 4; j++)
#pragma unroll
            for (int e = 0; e < 4; e++) ac.a[i][j][e] = 0.f;

    // 5-stage ring: prologue loads 4 stages, steady state keeps 3 in flight
    load_stage_1p(sb + 0 * Q_STG, A, B, m0, n0, 0 * BK, tid);
    load_stage_1p(sb + 1 * Q_STG, A, B, m0, n0, 1 * BK, tid);
    load_stage_1p(sb + 2 * Q_STG, A, B, m0, n0, 2 * BK, tid);
    load_stage_1p(sb + 3 * Q_STG, A, B, m0, n0, 3 * BK, tid);

    const uint32_t a_row_off = (uint32_t)((m_w + (lane & 15)) * ROWB) + ((lane >> 4) * 16);
    const uint32_t b_row_off = (uint32_t)((n_w + (lane & 7) + ((lane >> 4) << 3)) * ROWB)
                             + (((lane >> 3) & 1) * 16);

    for (int c = 0; c < NCHUNK; c++) {
        if (c >= NCHUNK - 4) CP_WAIT(0); else CP_WAIT(3);
        __syncthreads();    // write target (c+4)%5 == (c-1)%5, read last iter

        gemm_chunk(ac, sb + (uint32_t)(c % 5) * Q_STG, a_row_off, b_row_off);

        if (c + 4 < NCHUNK)
            load_stage_1p(sb + (uint32_t)((c + 4) % 5) * Q_STG, A, B, m0, n0,
                          (c + 4) * BK, tid);
    }

    const int rr = m0 + m_w + (lane >> 2);
#pragma unroll
    for (int i = 0; i < 4; i++) {
        const int r0 = rr + i * 16;
#pragma unroll
        for (int j = 0; j < 4; j++) {
            const int cc = n0 + n_w + j * 8 + 2 * (lane & 3);
            float2 bv = *(const float2*)&bias[cc];
            float* p = outp + (size_t)r0 * EMBD + cc;
            *(float2*)p = make_float2(ac.a[i][j][0] + bv.x, ac.a[i][j][1] + bv.y);
            *(float2*)(p + 8 * EMBD) =
                make_float2(ac.a[i][j][2] + bv.x, ac.a[i][j][3] + bv.y);
        }
    }
}

// ---------------------------------------------------------------------------
// Tensor-core causal flash attention — round-14 version (measured best).
// MAX-FREE softmax, single-rounded Q. S = Q16 K16 (1 product).
// P = 2^s via ex2.f16x2. Row sums via ones-MMA. O += P V (1 product).
// Br=64 (4 warps), Bc=64, 3 CTAs/SM, Q frags cached in regs.
// ---------------------------------------------------------------------------
#define ROWP 144      // 64 elems * 2B = 128B, +16B pad
#define SQ    0
#define STAGE0 9216
#define ASTG  18432   // per stage: K, V each 64*144=9216
#define OFF_K 0
#define OFF_V 9216
#define ATTN_SMEM (STAGE0 + 2 * ASTG)   // 46080
#define ONES_H2 0x3C003C00u

__global__ __launch_bounds__(128, 3) void attn_tc()
{
    extern __shared__ char smch[];
    const uint32_t sb = smem_u32(smch);

    const int tid  = threadIdx.x;
    const int lane = tid & 31;
    const int w    = tid >> 5;          // 0..3

    const int qt = gridDim.x - 1 - blockIdx.x;  // heavy tiles first
    const int h  = blockIdx.y;
    const int b  = blockIdx.z;
    const int q0 = qt * 64;
    const int kt_end = qt + 1;

    const size_t hb = ((size_t)(b * NHEAD + h)) * SEQ * HDIM;
    const __half* qg = g_q16 + hb + (size_t)q0 * HDIM;
    const __half* kg = g_k16 + hb;
    const __half* vg = g_v16 + hb;

    // --- issue Q loads (group 0): 64 rows x 8 chunks ---
#pragma unroll
    for (int i = 0; i < 4; i++) {
        int idx = tid + i * 128;       // 512
        int r = idx >> 3, ch = idx & 7;
        uint32_t d = sb + SQ + (uint32_t)(r * ROWP + ch * 16);
        cp16(d, qg + (size_t)r * HDIM + ch * 8);
    }
    CP_COMMIT();

    // --- prologue K/V stages for kt=0,1 (stage 1 may be empty group) ---
#pragma unroll
    for (int st = 0; st < 2; st++) {
        if (st < kt_end) {
            uint32_t base = sb + STAGE0 + st * ASTG;
            int k0 = st * 64;
#pragma unroll
            for (int i = 0; i < 4; i++) {
                int idx = tid + i * 128;   // 512: 64 rows x 8 chunks
                int r = idx >> 3, ch = idx & 7;
                uint32_t d = base + (uint32_t)(r * ROWP + ch * 16);
                size_t g = (size_t)(k0 + r) * HDIM + ch * 8;
                cp16(d + OFF_K, kg + g);
                cp16(d + OFF_V, vg + g);
            }
        }
        CP_COMMIT();
    }

    // --- Q A-frags into registers (cached across kt loop) ---
    CP_WAIT(2);
    __syncthreads();
    uint32_t qh[4][4];
    {
        uint32_t arow = sb + SQ + (uint32_t)((w * 16 + (lane & 15)) * ROWP) + ((lane >> 4) * 16);
#pragma unroll
        for (int t = 0; t < 4; t++)
            LDSM_X4(qh[t][0], qh[t][1], qh[t][2], qh[t][3], arow + t * 32);
    }

    float o[8][4];
#pragma unroll
    for (int j = 0; j < 8; j++)
#pragma unroll
        for (int e = 0; e < 4; e++) o[j][e] = 0.f;
    float l0s = 0.f, l1s = 0.f;

    const int warp_rmin = q0 + w * 16;
    const int row0 = warp_rmin + (lane >> 2);    // rows for c0/c1
    const int row1 = row0 + 8;                   // rows for c2/c3
    const int kcol = 2 * (lane & 3);

    for (int kt = 0; kt < kt_end; kt++) {
        if (kt + 1 < kt_end) CP_WAIT(1); else CP_WAIT(0);
        __syncthreads();

        const int k0 = kt * 64;
        const uint32_t stg = sb + STAGE0 + (kt & 1) * ASTG;

        // ---- S = Q K^T (single fp16 product; X4 K loads feed 2 k-slices) ----
        float s[8][4];
#pragma unroll
        for (int j = 0; j < 8; j++)
#pragma unroll
            for (int e = 0; e < 4; e++) s[j][e] = 0.f;

        const uint32_t kbase = stg + OFF_K + (uint32_t)((lane & 7) * ROWP) + ((lane >> 3) * 16);
#pragma unroll
        for (int tt = 0; tt < 2; tt++) {
#pragma unroll
            for (int j = 0; j < 8; j++) {
                uint32_t kb[4];
                uint32_t ba = kbase + (uint32_t)(j * 8 * ROWP) + tt * 64;
                LDSM_X4(kb[0], kb[1], kb[2], kb[3], ba);
                MMA_FP16(s[j], qh[2*tt][0],   qh[2*tt][1],   qh[2*tt][2],   qh[2*tt][3],   kb[0], kb[1]);
                MMA_FP16(s[j], qh[2*tt+1][0], qh[2*tt+1][1], qh[2*tt+1][2], qh[2*tt+1][3], kb[2], kb[3]);
            }
        }

        // ---- causal mask (diagonal tile only) ----
        if (kt == kt_end - 1) {
#pragma unroll
            for (int j = 0; j < 8; j++) {
                int kg2 = k0 + j * 8 + kcol;
                if (kg2     > row0) s[j][0] = -1e30f;
                if (kg2 + 1 > row0) s[j][1] = -1e30f;
                if (kg2     > row1) s[j][2] = -1e30f;
                if (kg2 + 1 > row1) s[j][3] = -1e30f;
            }
        }

        // ---- P = 2^s directly (max-free: logits bounded, fp16 holds it) ----
        uint32_t pa[4][4];
#pragma unroll
        for (int t = 0; t < 4; t++) {
            pa[t][0] = ex2h2(pack_h2(s[2*t][0],   s[2*t][1]));
            pa[t][1] = ex2h2(pack_h2(s[2*t][2],   s[2*t][3]));
            pa[t][2] = ex2h2(pack_h2(s[2*t+1][0], s[2*t+1][1]));
            pa[t][3] = ex2h2(pack_h2(s[2*t+1][2], s[2*t+1][3]));
        }

        // ---- row sums via ones-MMA (exact fp32, no shuffles) ----
        float ds[4] = {0.f, 0.f, 0.f, 0.f};
#pragma unroll
        for (int t = 0; t < 4; t++)
            MMA_FP16(ds, pa[t][0], pa[t][1], pa[t][2], pa[t][3], ONES_H2, ONES_H2);

        l0s += ds[0];
        l1s += ds[2];

        // ---- O += P @ V (single fp16 product, x4.trans) ----
        const uint32_t vbase = stg + OFF_V + (uint32_t)((lane & 15) * ROWP) + ((lane >> 4) * 16);
#pragma unroll
        for (int t = 0; t < 4; t++) {
            const uint32_t vt = vbase + (uint32_t)(t * 16 * ROWP);
#pragma unroll
            for (int jp = 0; jp < 4; jp++) {
                uint32_t v0, v1, v2, v3;
                LDSM_X4_T(v0, v1, v2, v3, vt + jp * 32);
                MMA_FP16(o[2*jp],   pa[t][0], pa[t][1], pa[t][2], pa[t][3], v0, v1);
                MMA_FP16(o[2*jp+1], pa[t][0], pa[t][1], pa[t][2], pa[t][3], v2, v3);
            }
        }

        __syncthreads();
        if (kt + 2 < kt_end) {
            uint32_t base = sb + STAGE0 + (kt & 1) * ASTG;
            int kn = (kt + 2) * 64;
#pragma unroll
            for (int i = 0; i < 4; i++) {
                int idx = tid + i * 128;
                int r = idx >> 3, ch = idx & 7;
                uint32_t d = base + (uint32_t)(r * ROWP + ch * 16);
                size_t g = (size_t)(kn + r) * HDIM + ch * 8;
                cp16(d + OFF_K, kg + g);
                cp16(d + OFF_V, vg + g);
            }
            CP_COMMIT();
        } else {
            CP_COMMIT();   // keep group count consistent with wait logic
        }
    }

    // ---- epilogue: O / l -> rounded fp16 y [B,T,C] ----
    const float rn0 = 1.0f / l0s;
    const float rn1 = 1.0f / l1s;
    const int cbase = h * HDIM + kcol;
#pragma unroll
    for (int j = 0; j < 8; j++) {
        int cc = cbase + j * 8;
        size_t i0 = ((size_t)b * SEQ + row0) * EMBD + cc;
        size_t i1 = ((size_t)b * SEQ + row1) * EMBD + cc;
        *(__half2*)&g_y16[i0] = __half2{__float2half_rn(o[j][0] * rn0),
                                        __float2half_rn(o[j][1] * rn0)};
        *(__half2*)&g_y16[i1] = __half2{__float2half_rn(o[j][2] * rn1),
                                        __float2half_rn(o[j][3] * rn1)};
    }
}

// ---------------------------------------------------------------------------
extern "C" void kernel_launch(void* const* d_in, const int* in_sizes, int n_in,
                              void* d_out, int out_size)
{
    const float* x  = (const float*)d_in[0];
    const float* Wq = (const float*)d_in[1];
    const float* Wk = (const float*)d_in[2];
    const float* Wv = (const float*)d_in[3];
    const float* Wp = (const float*)d_in[4];
    const float* bp = (const float*)d_in[5];
    float* out = (float*)d_out;

    cudaFuncSetAttribute(gemm_qkv,  cudaFuncAttributeMaxDynamicSharedMemorySize, GEMM1_SMEM);
    cudaFuncSetAttribute(gemm_proj, cudaFuncAttributeMaxDynamicSharedMemorySize, GEMM2_SMEM);
    cudaFuncSetAttribute(attn_tc,   cudaFuncAttributeMaxDynamicSharedMemorySize, ATTN_SMEM);

    __half *x16, *y16, *wt;
    cudaGetSymbolAddress((void**)&x16, g_x16);
    cudaGetSymbolAddress((void**)&y16, g_y16);
    cudaGetSymbolAddress((void**)&wt,  g_wt);

    // 1) fused prep: round x + transpose/round all 4 weight matrices
    prep_kernel<<<dim3(32, 32, 5), 256>>>(x, Wq, Wk, Wv, Wp);
    // 2) QKV projections (single product, 4-stage) -> Q (pre-scaled) / K / V
    gemm_qkv<<<dim3(EMBD / BN, MTOT / BM, 3), 256, GEMM1_SMEM>>>(x16, wt);
    // 3) tensor-core flash attention (round-14 best: ones-MMA row sums)
    attn_tc<<<dim3(SEQ / 64, NHEAD, BATCH), 128, ATTN_SMEM>>>();
    // 4) output projection + bias (single product, 5-stage deep prefetch)
    gemm_proj<<<dim3(EMBD / BN, MTOT / BM), 256, GEMM2_SMEM>>>(
        y16, wt + 3 * (size_t)EMBD * EMBD, bp, out);
}